// round 2
// baseline (speedup 1.0000x reference)
#include <cuda_runtime.h>
#include <math.h>

#define MAX_V 100000
#define MAX_B 1024

__device__ float g_invnorm[MAX_V];
__device__ float g_logit[2][MAX_B];

__device__ __forceinline__ float ex2f(float x) {
    float y;
    asm("ex2.approx.ftz.f32 %0, %1;" : "=f"(y) : "f"(x));
    return y;
}

// ---------------- per-vocab inverse norms ----------------
__global__ void norm_kernel(const float* __restrict__ emb, int V) {
    int row = blockIdx.x * 8 + (threadIdx.x >> 5);
    int lane = threadIdx.x & 31;
    if (row >= V) return;
    float4 v = *(const float4*)(emb + (size_t)row * 128 + lane * 4);
    float ss = v.x * v.x + v.y * v.y + v.z * v.z + v.w * v.w;
    #pragma unroll
    for (int o = 16; o > 0; o >>= 1)
        ss += __shfl_xor_sync(0xffffffffu, ss, o);
    if (lane == 0)
        g_invnorm[row] = (ss > 0.0f) ? rsqrtf(ss) : 0.0f;
}

// smem layout (floats)
#define SQS 68
#define SQT_F (128 * SQS)
#define SDT_F (128 * SQS)
#define MSM_F (64 * SQS)
#define RED_F (64 * 21)
#define AUX_F 64
#define SMEM_FLOATS (SQT_F + SDT_F + MSM_F + RED_F + AUX_F)

// 21 Gaussian kernels, log2-domain: k_i = 2^(A*m^2 + B_i*m + C_i)
// A = -50*log2(e); B_i = 100*log2(e)*mu_i; C_i = -50*log2(e)*mu_i^2
__device__ __forceinline__ void pool1(float m, float* acc) {
    float p = -72.13475204444817f * (m * m);
    #pragma unroll
    for (int i = 0; i < 20; ++i) {
        const double mu = -0.95 + 0.1 * (double)i;
        const float bc = (float)(144.26950408889634 * mu);
        const float cc = (float)(-72.13475204444817 * mu * mu);
        acc[i] += ex2f(fmaf(m, bc, cc) + p);
    }
    // exact kernel: sigma=0.001 -> -500000*log2(e)*(m-1)^2
    float t = m - 1.0f;
    acc[20] += ex2f(-721347.5204444817f * (t * t));
}

__global__ void __launch_bounds__(256, 2)
knrm_main(const int* __restrict__ q1, const int* __restrict__ d1,
          const int* __restrict__ q2, const int* __restrict__ d2,
          const float* __restrict__ emb,
          const float* __restrict__ W0, const float* __restrict__ b0,
          const float* __restrict__ W1, const float* __restrict__ b1,
          const float* __restrict__ W2, const float* __restrict__ b2)
{
    extern __shared__ float shbuf[];
    float* sqT = shbuf;                 // [128][SQS] k-major scaled q tile
    float* sdT = sqT + SQT_F;           // [128][SQS] k-major scaled d tile
    float* Msm = sdT + SDT_F;           // [64][SQS]  similarity tile
    float* red = Msm + MSM_F;           // [64][21]   per-q log1p values
    float* aux = red + RED_F;           // feats / mlp scratch

    const int b = blockIdx.x;
    const int pair = blockIdx.y;
    const int* qids = (pair ? q2 : q1) + b * 64;
    const int* dids = (pair ? d2 : d1) + b * 512;
    const int tid = threadIdx.x;

    // ---- load q tile: gather, scale by inv-norm, transpose to k-major ----
    {
        int rr = tid >> 3;   // 0..31
        int cc = tid & 7;    // 0..7 (float4 chunk)
        for (int row = rr; row < 64; row += 32) {
            int id = qids[row];
            float inv = g_invnorm[id];
            const float4* src = (const float4*)(emb + (size_t)id * 128);
            #pragma unroll
            for (int it = 0; it < 4; ++it) {
                int c = it * 8 + cc;
                float4 v = src[c];
                int k = c * 4;
                sqT[(k + 0) * SQS + row] = v.x * inv;
                sqT[(k + 1) * SQS + row] = v.y * inv;
                sqT[(k + 2) * SQS + row] = v.z * inv;
                sqT[(k + 3) * SQS + row] = v.w * inv;
            }
        }
    }

    float acc[21];
    #pragma unroll
    for (int i = 0; i < 21; ++i) acc[i] = 0.0f;

    const int tx = tid & 15, ty = tid >> 4;
    const int q0 = ty * 4, d0 = tx * 4;
    const int pq = tid >> 2, pg = tid & 3;

    __syncthreads();

    for (int tile = 0; tile < 8; ++tile) {
        // ---- load d tile ----
        {
            int rr = tid >> 3;
            int cc = tid & 7;
            for (int row = rr; row < 64; row += 32) {
                int id = dids[tile * 64 + row];
                float inv = g_invnorm[id];
                const float4* src = (const float4*)(emb + (size_t)id * 128);
                #pragma unroll
                for (int it = 0; it < 4; ++it) {
                    int c = it * 8 + cc;
                    float4 v = src[c];
                    int k = c * 4;
                    sdT[(k + 0) * SQS + row] = v.x * inv;
                    sdT[(k + 1) * SQS + row] = v.y * inv;
                    sdT[(k + 2) * SQS + row] = v.z * inv;
                    sdT[(k + 3) * SQS + row] = v.w * inv;
                }
            }
        }
        __syncthreads();

        // ---- 64x64x128 fp32 GEMM, 4x4 register tiles ----
        {
            float c16[16];
            #pragma unroll
            for (int i = 0; i < 16; ++i) c16[i] = 0.0f;
            const float* aq = sqT + q0;
            const float* ad = sdT + d0;
            #pragma unroll 8
            for (int k = 0; k < 128; ++k) {
                float4 av = *(const float4*)(aq + k * SQS);
                float4 bv = *(const float4*)(ad + k * SQS);
                c16[0]  = fmaf(av.x, bv.x, c16[0]);
                c16[1]  = fmaf(av.x, bv.y, c16[1]);
                c16[2]  = fmaf(av.x, bv.z, c16[2]);
                c16[3]  = fmaf(av.x, bv.w, c16[3]);
                c16[4]  = fmaf(av.y, bv.x, c16[4]);
                c16[5]  = fmaf(av.y, bv.y, c16[5]);
                c16[6]  = fmaf(av.y, bv.z, c16[6]);
                c16[7]  = fmaf(av.y, bv.w, c16[7]);
                c16[8]  = fmaf(av.z, bv.x, c16[8]);
                c16[9]  = fmaf(av.z, bv.y, c16[9]);
                c16[10] = fmaf(av.z, bv.z, c16[10]);
                c16[11] = fmaf(av.z, bv.w, c16[11]);
                c16[12] = fmaf(av.w, bv.x, c16[12]);
                c16[13] = fmaf(av.w, bv.y, c16[13]);
                c16[14] = fmaf(av.w, bv.z, c16[14]);
                c16[15] = fmaf(av.w, bv.w, c16[15]);
            }
            #pragma unroll
            for (int qi = 0; qi < 4; ++qi) {
                float4 w = make_float4(c16[qi * 4 + 0], c16[qi * 4 + 1],
                                       c16[qi * 4 + 2], c16[qi * 4 + 3]);
                *(float4*)(Msm + (q0 + qi) * SQS + d0) = w;
            }
        }
        __syncthreads();

        // ---- pooling: thread = (q row, 16-wide d chunk) ----
        {
            const float* mrow = Msm + pq * SQS + pg * 16;
            #pragma unroll 1
            for (int j = 0; j < 4; ++j) {
                float4 m4 = *(const float4*)(mrow + j * 4);
                pool1(m4.x, acc);
                pool1(m4.y, acc);
                pool1(m4.z, acc);
                pool1(m4.w, acc);
            }
        }
        __syncthreads();
    }

    // reduce partial kernel sums across the 4 groups per q row
    #pragma unroll
    for (int i = 0; i < 21; ++i) {
        float v = acc[i];
        v += __shfl_xor_sync(0xffffffffu, v, 1);
        v += __shfl_xor_sync(0xffffffffu, v, 2);
        acc[i] = v;
    }
    if (pg == 0) {
        #pragma unroll
        for (int i = 0; i < 21; ++i)
            red[pq * 21 + i] = log1pf(acc[i]);
    }
    __syncthreads();

    // feats: sum log1p over q, then tiny MLP
    float* fe = aux;        // 21
    float* h0 = aux + 24;   // 10
    float* h1 = aux + 40;   // 5
    if (tid < 21) {
        float s = 0.0f;
        #pragma unroll 4
        for (int q = 0; q < 64; ++q) s += red[q * 21 + tid];
        fe[tid] = s;
    }
    __syncthreads();
    if (tid < 10) {
        float h = b0[tid];
        #pragma unroll
        for (int j = 0; j < 21; ++j) h = fmaf(W0[tid * 21 + j], fe[j], h);
        h0[tid] = fmaxf(h, 0.0f);
    }
    __syncthreads();
    if (tid < 5) {
        float h = b1[tid];
        #pragma unroll
        for (int j = 0; j < 10; ++j) h = fmaf(W1[tid * 10 + j], h0[j], h);
        h1[tid] = fmaxf(h, 0.0f);
    }
    __syncthreads();
    if (tid == 0) {
        float l = b2[0];
        #pragma unroll
        for (int j = 0; j < 5; ++j) l = fmaf(W2[j], h1[j], l);
        g_logit[pair][b] = l;
    }
}

__global__ void final_kernel(float* __restrict__ out, int B) {
    int i = blockIdx.x * blockDim.x + threadIdx.x;
    if (i < B) {
        float x = g_logit[0][i] - g_logit[1][i];
        out[i] = 1.0f / (1.0f + expf(-x));
    }
}

extern "C" void kernel_launch(void* const* d_in, const int* in_sizes, int n_in,
                              void* d_out, int out_size) {
    const int* q1 = (const int*)d_in[0];
    const int* d1 = (const int*)d_in[1];
    const int* q2 = (const int*)d_in[2];
    const int* d2 = (const int*)d_in[3];
    const float* emb = (const float*)d_in[4];
    const float* W0 = (const float*)d_in[5];
    const float* b0 = (const float*)d_in[6];
    const float* W1 = (const float*)d_in[7];
    const float* b1 = (const float*)d_in[8];
    const float* W2 = (const float*)d_in[9];
    const float* b2 = (const float*)d_in[10];

    int B = in_sizes[0] / 64;
    int V = in_sizes[4] / 128;

    norm_kernel<<<(V + 7) / 8, 256>>>(emb, V);

    size_t smem = SMEM_FLOATS * sizeof(float);
    cudaFuncSetAttribute(knrm_main, cudaFuncAttributeMaxDynamicSharedMemorySize, (int)smem);
    knrm_main<<<dim3(B, 2), 256, smem>>>(q1, d1, q2, d2, emb, W0, b0, W1, b1, W2, b2);

    final_kernel<<<(B + 255) / 256, 256>>>((float*)d_out, B);
}